// round 11
// baseline (speedup 1.0000x reference)
#include <cuda_runtime.h>
#include <math_constants.h>
#include <math.h>

#define BB 32
#define NN 1024
#define FF 10
#define DD 64
#define MM 4
#define RR 8
#define KK 20
#define NROWS (BB*NN)           // 32768
#define BN_EPS 1e-5f
#define HCHUNK 16
#define SCT 1032                // padded row stride for score smem

typedef unsigned long long ull;

// ---------------- scratch (device globals; no runtime allocation) ----------------
__device__ float g_hit[NROWS*DD];
__device__ float g_xlin[NROWS*DD];
__device__ float g_eit[NROWS];
__device__ float g_emax[BB];
__device__ float g_eden[BB];
__device__ float g_hpart[HCHUNK*BB*DD];
__device__ float g_pih[BB*MM];
__device__ float g_proto[MM*NN*DD];
__device__ float g_mixed[NROWS*DD];
__device__ float g_si[NROWS];
__device__ float g_sj[NROWS];
__device__ float g_tv[NROWS*KK];
__device__ int   g_ti[NROWS*KK];
__device__ float g_gnn[NROWS*DD];
__device__ double g_stats[4*DD];

// ---------------- helpers ----------------
__device__ __forceinline__ float nanfix(float x){
  if (isnan(x)) return 0.f;
  if (isinf(x)) return x > 0.f ? 1e4f : -1e4f;
  return x;
}
__device__ __forceinline__ float lrelu(float x){ return x >= 0.f ? x : 0.2f*x; }

__device__ __forceinline__ ull ffma2(ull a, ull b, ull c){
  ull d;
  asm("fma.rn.f32x2 %0, %1, %2, %3;" : "=l"(d) : "l"(a), "l"(b), "l"(c));
  return d;
}
__device__ __forceinline__ ull dup2(float a){
  ull r;
  asm("mov.b64 %0, {%1, %1};" : "=l"(r) : "f"(a));
  return r;
}
__device__ __forceinline__ void unpack2(ull v, float& lo, float& hi){
  asm("mov.b64 {%0, %1}, %2;" : "=f"(lo), "=f"(hi) : "l"(v));
}

// ---------------- K1: cond MLP (h_it, e_it) + x_lin (warp per row) + stats zero ----------------
__global__ void __launch_bounds__(256) k_cond(const float* __restrict__ data,
    const float* __restrict__ Wc, const float* __restrict__ bc,
    const float* __restrict__ Wap, const float* __restrict__ bap,
    const float* __restrict__ Wav, const float* __restrict__ Wg){
  __shared__ float Wap_s[DD*DD];
  __shared__ float Wc_s[FF*DD];
  __shared__ float Wg_s[FF*DD];
  __shared__ float hbuf[8][DD];
  int t = threadIdx.x;
  if (blockIdx.x == 0) g_stats[t] = 0.0;      // folded k_zero
  for (int e = t; e < DD*DD; e += 256) Wap_s[e] = Wap[e];
  for (int e = t; e < FF*DD; e += 256){ Wc_s[e] = Wc[e]; Wg_s[e] = Wg[e]; }
  __syncthreads();
  int warp = t >> 5, lane = t & 31;
  int row = blockIdx.x*8 + warp;
  const float* dr = data + row*FF;
  float x[FF];
  #pragma unroll
  for (int f = 0; f < FF; f++) x[f] = dr[f];
  int d0 = lane, d1 = lane + 32;
  float h0 = bc[d0], h1 = bc[d1], xl0 = 0.f, xl1 = 0.f;
  #pragma unroll
  for (int f = 0; f < FF; f++){
    h0  = fmaf(x[f], Wc_s[f*DD+d0], h0);
    h1  = fmaf(x[f], Wc_s[f*DD+d1], h1);
    xl0 = fmaf(x[f], Wg_s[f*DD+d0], xl0);
    xl1 = fmaf(x[f], Wg_s[f*DD+d1], xl1);
  }
  g_hit[row*DD+d0] = h0;  g_hit[row*DD+d1] = h1;
  g_xlin[row*DD+d0] = xl0; g_xlin[row*DD+d1] = xl1;
  hbuf[warp][d0] = h0; hbuf[warp][d1] = h1;
  __syncwarp();
  float a0 = bap[d0], a1 = bap[d1];
  #pragma unroll 16
  for (int e = 0; e < DD; e++){
    float he = hbuf[warp][e];
    a0 = fmaf(he, Wap_s[e*DD+d0], a0);
    a1 = fmaf(he, Wap_s[e*DD+d1], a1);
  }
  a0 = lrelu(a0); a1 = lrelu(a1);
  float ts = a0*Wav[d0] + a1*Wav[d1];
  #pragma unroll
  for (int off = 16; off > 0; off >>= 1) ts += __shfl_xor_sync(0xffffffffu, ts, off);
  if (lane == 0) g_eit[row] = nanfix(ts);
}

// ---------------- K2a: per-batch softmax max + denom ----------------
__global__ void __launch_bounds__(256) k_esoft(){
  int b = blockIdx.x, t = threadIdx.x;
  __shared__ float red[256];
  const float* e = g_eit + b*NN;
  float m = fmaxf(e[t], fmaxf(e[t+256], fmaxf(e[t+512], e[t+768])));
  red[t] = m; __syncthreads();
  for (int s = 128; s > 0; s >>= 1){ if (t < s) red[t] = fmaxf(red[t], red[t+s]); __syncthreads(); }
  float mx = red[0];
  __syncthreads();
  float se = expf(e[t]-mx) + expf(e[t+256]-mx) + expf(e[t+512]-mx) + expf(e[t+768]-mx);
  red[t] = se; __syncthreads();
  for (int s = 128; s > 0; s >>= 1){ if (t < s) red[t] += red[t+s]; __syncthreads(); }
  if (t == 0){ g_emax[b] = mx; g_eden[b] = red[0]; }
}

// ---------------- K2b: h_sys partial weighted sums ----------------
__global__ void __launch_bounds__(256) k_hsys(){
  int chunk = blockIdx.x;
  int b = blockIdx.y;
  int t = threadIdx.x;
  int d = t & 63, r4 = t >> 6;
  __shared__ float red[256];
  float mx = g_emax[b];
  int n0 = chunk*64;
  const float* e = g_eit + b*NN + n0;
  const float* h = g_hit + ((size_t)b*NN + n0)*DD;
  float acc = 0.f;
  #pragma unroll 4
  for (int r = r4; r < 64; r += 4)
    acc = fmaf(expf(e[r]-mx), h[r*DD + d], acc);
  red[t] = acc; __syncthreads();
  if (t < 64)
    g_hpart[(chunk*BB + b)*DD + d] = red[d] + red[d+64] + red[d+128] + red[d+192];
}

// ---------------- K2c: finalize h_sys + gumbel top-2 routing ----------------
__global__ void __launch_bounds__(64) k_route(const float* __restrict__ Wr,
    const float* __restrict__ br, const float* __restrict__ gum,
    float* __restrict__ hs_out, float* __restrict__ ps_out){
  int b = blockIdx.x, t = threadIdx.x;
  __shared__ float shs[DD];
  __shared__ float slog[MM];
  float s = 0.f;
  #pragma unroll
  for (int c = 0; c < HCHUNK; c++) s += g_hpart[(c*BB + b)*DD + t];
  float hs = s / g_eden[b];
  shs[t] = hs;
  hs_out[b*DD + t] = hs;
  __syncthreads();
  if (t < MM){
    float lg = br[t] + gum[b*MM + t];
    #pragma unroll 8
    for (int dd2 = 0; dd2 < DD; dd2++) lg = fmaf(shs[dd2], Wr[dd2*MM + t], lg);
    slog[t] = lg;
  }
  __syncthreads();
  if (t == 0){
    float mm = slog[0];
    #pragma unroll
    for (int i = 1; i < MM; i++) mm = fmaxf(mm, slog[i]);
    float p[MM]; float sp = 0.f;
    #pragma unroll
    for (int i = 0; i < MM; i++){ p[i] = expf(slog[i] - mm); sp += p[i]; }
    #pragma unroll
    for (int i = 0; i < MM; i++){ p[i] /= sp; ps_out[b*MM + i] = p[i]; }
    int i1 = 0;
    #pragma unroll
    for (int i = 1; i < MM; i++) if (p[i] > p[i1]) i1 = i;
    int i2 = -1;
    #pragma unroll
    for (int i = 0; i < MM; i++){
      if (i == i1) continue;
      if (i2 < 0 || p[i] > p[i2]) i2 = i;
    }
    float nrm = fmaxf(p[i1] + p[i2], 1e-12f);
    #pragma unroll
    for (int i = 0; i < MM; i++) g_pih[b*MM + i] = 0.f;
    g_pih[b*MM + i1] = p[i1] / nrm;
    g_pih[b*MM + i2] = p[i2] / nrm;
  }
}

// ---------------- K3a: expert prototypes ----------------
__global__ void __launch_bounds__(256) k_proto(const float* __restrict__ ebase,
    const float* __restrict__ lru, const float* __restrict__ lrv){
  int t = threadIdx.x, warp = t >> 5, lane = t & 31;
  int rown = blockIdx.x*8 + warp;
  int m = rown >> 10, n = rown & (NN-1);
  int d0 = lane, d1 = lane + 32;
  float p0 = ebase[n*DD+d0], p1 = ebase[n*DD+d1];
  #pragma unroll
  for (int r = 0; r < RR; r++){
    float u = lru[rown*RR + r];
    p0 = fmaf(u, lrv[(m*RR+r)*DD+d0], p0);
    p1 = fmaf(u, lrv[(m*RR+r)*DD+d1], p1);
  }
  g_proto[rown*DD+d0] = p0;
  g_proto[rown*DD+d1] = p1;
}

// ---------------- K3b: mixed = pi @ proto, + s_i / s_j ----------------
__global__ void __launch_bounds__(256) k_mixed(const float* __restrict__ ai,
    const float* __restrict__ aj, const float* __restrict__ aei,
    const float* __restrict__ aej){
  int t = threadIdx.x, warp = t >> 5, lane = t & 31;
  int row = blockIdx.x*8 + warp;
  int b = row >> 10, n = row & (NN-1);
  int d0 = lane, d1 = lane + 32;
  float pi0 = g_pih[b*MM+0], pi1 = g_pih[b*MM+1];
  float pi2 = g_pih[b*MM+2], pi3 = g_pih[b*MM+3];
  float mx0, mx1;
  {
    const float* p0 = g_proto + (0*NN+n)*DD;
    const float* p1 = g_proto + (1*NN+n)*DD;
    const float* p2 = g_proto + (2*NN+n)*DD;
    const float* p3 = g_proto + (3*NN+n)*DD;
    mx0 = pi0*p0[d0] + pi1*p1[d0] + pi2*p2[d0] + pi3*p3[d0];
    mx1 = pi0*p0[d1] + pi1*p1[d1] + pi2*p2[d1] + pi3*p3[d1];
  }
  mx0 = nanfix(mx0); mx1 = nanfix(mx1);
  g_mixed[row*DD+d0] = mx0;
  g_mixed[row*DD+d1] = mx1;
  float xl0 = g_xlin[row*DD+d0], xl1 = g_xlin[row*DD+d1];
  float r1 = xl0*ai[d0] + mx0*aei[d0] + xl1*ai[d1] + mx1*aei[d1];
  float r2 = xl0*aj[d0] + mx0*aej[d0] + xl1*aj[d1] + mx1*aej[d1];
  #pragma unroll
  for (int off = 16; off > 0; off >>= 1){
    r1 += __shfl_xor_sync(0xffffffffu, r1, off);
    r2 += __shfl_xor_sync(0xffffffffu, r2, off);
  }
  if (lane == 0){ g_si[row] = r1; g_sj[row] = r2; }
}

// ---------------- K4: FUSED scores (32 rows x 1024) + top-20, no global scores ----------------
// smem: sc[32][1032] | Bs[64][132] | Ast[64][36]   = 175104 bytes
__global__ void __launch_bounds__(256) k_sctop(){
  extern __shared__ float smem[];
  float* sc  = smem;                  // 32*1032
  float* Bs  = smem + 32*SCT;         // 64*132
  float* Ast = Bs + 64*132;           // 64*36
  int b = blockIdx.y;
  int bi = blockIdx.x * 32;
  int t = threadIdx.x;
  int tx = t & 31, ty = t >> 5;       // warp == ty
  const float* mixedb = g_mixed + (size_t)b*NN*DD;

  // load A tile (rows bi..bi+31) transposed into Ast[k][i]; lanes map to i -> conflict-free STS
  {
    int i = t & 31;
    int k0 = (t >> 5) * 8;
    const float4* a4 = (const float4*)(mixedb + (size_t)(bi+i)*DD + k0);
    float4 v0 = a4[0], v1 = a4[1];
    Ast[(k0+0)*36+i]=v0.x; Ast[(k0+1)*36+i]=v0.y; Ast[(k0+2)*36+i]=v0.z; Ast[(k0+3)*36+i]=v0.w;
    Ast[(k0+4)*36+i]=v1.x; Ast[(k0+5)*36+i]=v1.y; Ast[(k0+6)*36+i]=v1.z; Ast[(k0+7)*36+i]=v1.w;
  }
  // prefetch B chunk 0 into registers: j = t&127 (lane-contiguous STS later), kh = (t>>7)*32
  int bj = t & 127, bkh = (t >> 7) * 32;
  float4 pb[8];
  {
    const float4* b4 = (const float4*)(mixedb + (size_t)bj*DD + bkh);
    #pragma unroll
    for (int q = 0; q < 8; q++) pb[q] = b4[q];
  }

  for (int ch = 0; ch < 8; ch++){
    // store prefetched B chunk transposed into Bs[k][j]
    #pragma unroll
    for (int q = 0; q < 8; q++){
      int k = bkh + q*4;
      Bs[(k+0)*132+bj]=pb[q].x; Bs[(k+1)*132+bj]=pb[q].y;
      Bs[(k+2)*132+bj]=pb[q].z; Bs[(k+3)*132+bj]=pb[q].w;
    }
    __syncthreads();
    // prefetch next chunk (latency hidden behind compute)
    if (ch < 7){
      const float4* b4 = (const float4*)(mixedb + (size_t)((ch+1)*128 + bj)*DD + bkh);
      #pragma unroll
      for (int q = 0; q < 8; q++) pb[q] = b4[q];
    }
    // compute 32 x 128: microtile 4i x 4j per thread
    ull acc[4][2];
    #pragma unroll
    for (int ii = 0; ii < 4; ii++){ acc[ii][0] = 0ull; acc[ii][1] = 0ull; }
    #pragma unroll 16
    for (int k = 0; k < 64; k++){
      float4 av = *(const float4*)&Ast[k*36 + ty*4];          // broadcast
      ulonglong2 bv = *(const ulonglong2*)&Bs[k*132 + tx*4];  // conflict-free
      ull a0 = dup2(av.x), a1 = dup2(av.y), a2 = dup2(av.z), a3 = dup2(av.w);
      acc[0][0] = ffma2(a0, bv.x, acc[0][0]); acc[0][1] = ffma2(a0, bv.y, acc[0][1]);
      acc[1][0] = ffma2(a1, bv.x, acc[1][0]); acc[1][1] = ffma2(a1, bv.y, acc[1][1]);
      acc[2][0] = ffma2(a2, bv.x, acc[2][0]); acc[2][1] = ffma2(a2, bv.y, acc[2][1]);
      acc[3][0] = ffma2(a3, bv.x, acc[3][0]); acc[3][1] = ffma2(a3, bv.y, acc[3][1]);
    }
    #pragma unroll
    for (int ii = 0; ii < 4; ii++){
      float v0,v1,v2,v3;
      unpack2(acc[ii][0], v0, v1);
      unpack2(acc[ii][1], v2, v3);
      *(float4*)&sc[(ty*4+ii)*SCT + ch*128 + tx*4] = make_float4(v0,v1,v2,v3);
    }
    __syncthreads();
  }

  // ---- top-20 per row from smem; warp ty handles rows ty*4 .. ty*4+3 ----
  int lane = tx;
  for (int ri = 0; ri < 4; ri++){
    int i = ty*4 + ri;
    int grow = b*NN + bi + i;
    const float* srow = sc + i*SCT;
    float v[32];
    #pragma unroll
    for (int s = 0; s < 32; s++) v[s] = srow[s*32 + lane];   // j = s*32 + lane
    // per-lane sorted top-3 cache (value desc, lower slot first on tie via strict >)
    float c0v = -CUDART_INF_F, c1v = -CUDART_INF_F, c2v = -CUDART_INF_F;
    int c0s = 0, c1s = 0, c2s = 0;
    #pragma unroll
    for (int s = 0; s < 32; s++){
      float x = v[s];
      if (x > c2v){
        if (x > c1v){
          c2v = c1v; c2s = c1s;
          if (x > c0v){ c1v = c0v; c1s = c0s; c0v = x; c0s = s; }
          else        { c1v = x; c1s = s; }
        } else { c2v = x; c2s = s; }
      }
    }
    unsigned used = 0u;
    int p = 0;
    int cs = c0s;
    float candv = c0v;
    int candg = c0s*32 + lane;
    float* otv = g_tv + grow*KK;
    int*   oti = g_ti + grow*KK;
    for (int k = 0; k < KK; k++){
      float bv = candv; int bg = candg;
      #pragma unroll
      for (int off = 16; off > 0; off >>= 1){
        float ov = __shfl_xor_sync(0xffffffffu, bv, off);
        int   og = __shfl_xor_sync(0xffffffffu, bg, off);
        if (ov > bv || (ov == bv && og < bg)){ bv = ov; bg = og; }
      }
      if (lane == 0){ otv[k] = bv; oti[k] = bg; }
      if (bg == candg){
        used |= 1u << cs;
        p++;
        if (p == 1){ cs = c1s; candv = c1v; candg = c1s*32 + lane; }
        else if (p == 2){ cs = c2s; candv = c2v; candg = c2s*32 + lane; }
        else {
          candv = -CUDART_INF_F; cs = -1;
          #pragma unroll
          for (int s = 0; s < 32; s++){
            if (!((used >> s) & 1u)){
              float x = v[s];
              if (x > candv){ candv = x; cs = s; }
            }
          }
          candg = (cs >= 0) ? (cs*32 + lane) : ((1<<20) + lane);
        }
      }
    }
  }
}

// ---------------- K6: GAT attention + aggregation ----------------
__global__ void __launch_bounds__(256) k_gat(const float* __restrict__ bgnn){
  __shared__ int   sidx[4][KK];
  __shared__ float stv[4][KK];
  __shared__ float sw[4][KK+1];
  int t = threadIdx.x;
  int g = t >> 6, d = t & 63;
  int row = blockIdx.x*4 + g;
  int b = row >> 10, i = row & (NN-1);
  if (d < KK){
    stv[g][d] = g_tv[row*KK + d];
    sidx[g][d] = g_ti[row*KK + d];
  }
  __syncthreads();
  if (d < 32){
    int lane = d;
    float si = g_si[row];
    float a;
    if (lane < KK){
      int j = sidx[g][lane];
      float sj = g_sj[b*NN + j];
      a = (j == i) ? -CUDART_INF_F : lrelu(si + sj);
    } else if (lane == KK){
      a = lrelu(si + g_sj[row]);
    } else a = -CUDART_INF_F;
    float m = a;
    #pragma unroll
    for (int off = 16; off > 0; off >>= 1) m = fmaxf(m, __shfl_xor_sync(0xffffffffu, m, off));
    float e = (lane <= KK) ? expf(a - m) : 0.f;
    float s = e;
    #pragma unroll
    for (int off = 16; off > 0; off >>= 1) s += __shfl_xor_sync(0xffffffffu, s, off);
    float att = e / s;
    float tvv = (lane < KK) ? stv[g][lane] : -CUDART_INF_F;
    float m2 = tvv;
    #pragma unroll
    for (int off = 16; off > 0; off >>= 1) m2 = fmaxf(m2, __shfl_xor_sync(0xffffffffu, m2, off));
    float e2 = (lane < KK) ? expf(tvv - m2) : 0.f;
    float s2 = e2;
    #pragma unroll
    for (int off = 16; off > 0; off >>= 1) s2 += __shfl_xor_sync(0xffffffffu, s2, off);
    if (lane <= KK)
      sw[g][lane] = (lane < KK) ? att * (e2 / s2) : att;
  }
  __syncthreads();
  float acc = sw[g][KK] * g_xlin[row*DD + d];
  #pragma unroll 4
  for (int k = 0; k < KK; k++)
    acc = fmaf(sw[g][k], g_xlin[((size_t)b*NN + sidx[g][k])*DD + d], acc);
  acc += bgnn[d];
  g_gnn[row*DD + d] = acc;
}

// ---------------- K7: BN1 stats ----------------
__global__ void __launch_bounds__(256) k_stats1(){
  __shared__ float ss[256], sq[256];
  int t = threadIdx.x;
  int c = t >> 6, d = t & 63;
  float s = 0.f, q = 0.f;
  int base = blockIdx.x * 256;
  for (int it = 0; it < 64; it++){
    int row = base + it*4 + c;
    float x = g_gnn[row*DD + d];
    s += x;
    q = fmaf(x, x, q);
  }
  ss[t] = s; sq[t] = q;
  __syncthreads();
  if (t < 64){
    double S = (double)ss[t] + ss[t+64] + ss[t+128] + ss[t+192];
    double Q = (double)sq[t] + sq[t+64] + sq[t+128] + sq[t+192];
    atomicAdd(&g_stats[d], S);
    atomicAdd(&g_stats[DD + d], Q);
  }
}

// ---------------- K8: BN2 stats from recomputed y ----------------
__global__ void __launch_bounds__(256) k_bn1mul(const float* __restrict__ g1,
    const float* __restrict__ be1, const float* __restrict__ net){
  __shared__ float ss[256], sq[256];
  int t = threadIdx.x;
  int c = t >> 6, d = t & 63;
  double inv = 1.0 / (double)NROWS;
  double mu = g_stats[d] * inv;
  double var = g_stats[DD + d] * inv - mu*mu;
  float scale = g1[d] * rsqrtf((float)var + BN_EPS);
  float shift = be1[d] - (float)mu * scale;
  float s = 0.f, q = 0.f;
  int base = blockIdx.x * 256;
  for (int it = 0; it < 64; it++){
    int row = base + it*4 + c;
    float x = g_gnn[row*DD + d];
    float gv = fmaxf(fmaf(x, scale, shift), 0.f);
    float y = gv * net[(row & (NN-1))*DD + d];
    s += y;
    q = fmaf(y, y, q);
  }
  ss[t] = s; sq[t] = q;
  __syncthreads();
  if (t < 64){
    double S = (double)ss[t] + ss[t+64] + ss[t+128] + ss[t+192];
    double Q = (double)sq[t] + sq[t+64] + sq[t+128] + sq[t+192];
    atomicAdd(&g_stats[2*DD + d], S);
    atomicAdd(&g_stats[3*DD + d], Q);
  }
}

// ---------------- K9: BN2 + relu + output head ----------------
__global__ void __launch_bounds__(256) k_head(const float* __restrict__ g1,
    const float* __restrict__ be1, const float* __restrict__ net,
    const float* __restrict__ g2, const float* __restrict__ be2,
    const float* __restrict__ Wo, const float* __restrict__ bo,
    float* __restrict__ dout){
  int warp = threadIdx.x >> 5;
  int lane = threadIdx.x & 31;
  int row = blockIdx.x*8 + warp;
  int n = row & (NN-1);
  double inv = 1.0 / (double)NROWS;
  float acc = 0.f;
  #pragma unroll
  for (int h = 0; h < 2; h++){
    int d = lane + h*32;
    double mu1 = g_stats[d] * inv;
    double var1 = g_stats[DD + d] * inv - mu1*mu1;
    float sc1 = g1[d] * rsqrtf((float)var1 + BN_EPS);
    float sh1 = be1[d] - (float)mu1 * sc1;
    double mu2 = g_stats[2*DD + d] * inv;
    double var2 = g_stats[3*DD + d] * inv - mu2*mu2;
    float sc2 = g2[d] * rsqrtf((float)var2 + BN_EPS);
    float sh2 = be2[d] - (float)mu2 * sc2;
    float x = g_gnn[row*DD + d];
    float gv = fmaxf(fmaf(x, sc1, sh1), 0.f);
    float y = gv * net[n*DD + d];
    float r = fmaxf(fmaf(y, sc2, sh2), 0.f);
    acc = fmaf(r, Wo[d], acc);
  }
  #pragma unroll
  for (int off = 16; off > 0; off >>= 1)
    acc += __shfl_down_sync(0xffffffffu, acc, off);
  if (lane == 0) dout[row] = acc + bo[0];
}

// ---------------- launch ----------------
extern "C" void kernel_launch(void* const* d_in, const int* in_sizes, int n_in,
                              void* d_out, int out_size) {
  const float* data   = (const float*)d_in[0];
  const float* gum    = (const float*)d_in[1];
  const float* Wc     = (const float*)d_in[2];
  const float* bc     = (const float*)d_in[3];
  const float* Wap    = (const float*)d_in[4];
  const float* bap    = (const float*)d_in[5];
  const float* Wav    = (const float*)d_in[6];
  const float* Wr     = (const float*)d_in[7];
  const float* br     = (const float*)d_in[8];
  const float* ebase  = (const float*)d_in[9];
  const float* lru    = (const float*)d_in[10];
  const float* lrv    = (const float*)d_in[11];
  const float* Wg     = (const float*)d_in[12];
  const float* ai     = (const float*)d_in[13];
  const float* aj     = (const float*)d_in[14];
  const float* aei    = (const float*)d_in[15];
  const float* aej    = (const float*)d_in[16];
  const float* bgnn   = (const float*)d_in[17];
  const float* g1     = (const float*)d_in[18];
  const float* be1    = (const float*)d_in[19];
  const float* net    = (const float*)d_in[20];
  const float* g2     = (const float*)d_in[21];
  const float* be2    = (const float*)d_in[22];
  const float* Wo     = (const float*)d_in[23];
  const float* bo     = (const float*)d_in[24];

  float* out    = (float*)d_out;              // [B,N]   32768
  float* hs_out = out + NROWS;                // [B,D]   2048
  float* ps_out = hs_out + BB*DD;             // [B,M]   128

  const int SCT_SMEM = (32*SCT + 64*132 + 64*36) * 4;   // 175104 B
  cudaFuncSetAttribute(k_sctop, cudaFuncAttributeMaxDynamicSharedMemorySize, SCT_SMEM);

  k_cond<<<NROWS/8, 256>>>(data, Wc, bc, Wap, bap, Wav, Wg);
  k_proto<<<MM*NN/8, 256>>>(ebase, lru, lrv);
  k_esoft<<<BB, 256>>>();
  k_hsys<<<dim3(HCHUNK, BB), 256>>>();
  k_route<<<BB, 64>>>(Wr, br, gum, hs_out, ps_out);
  k_mixed<<<NROWS/8, 256>>>(ai, aj, aei, aej);
  k_sctop<<<dim3(NN/32, BB), 256, SCT_SMEM>>>();
  k_gat<<<NROWS/4, 256>>>(bgnn);
  k_stats1<<<128, 256>>>();
  k_bn1mul<<<128, 256>>>(g1, be1, net);
  k_head<<<NROWS/8, 256>>>(g1, be1, net, g2, be2, Wo, bo, out);
}

// round 12
// speedup vs baseline: 1.4334x; 1.4334x over previous
#include <cuda_runtime.h>
#include <math_constants.h>
#include <math.h>

#define BB 32
#define NN 1024
#define FF 10
#define DD 64
#define MM 4
#define RR 8
#define KK 20
#define NROWS (BB*NN)           // 32768
#define BN_EPS 1e-5f
#define HCHUNK 16
#define HALFB 16                // batches per scores/topk chunk (64 MiB, L2-resident)

typedef unsigned long long ull;

// ---------------- scratch (device globals; no runtime allocation) ----------------
__device__ float g_hit[NROWS*DD];
__device__ float g_xlin[NROWS*DD];
__device__ float g_eit[NROWS];
__device__ float g_emax[BB];
__device__ float g_eden[BB];
__device__ float g_hpart[HCHUNK*BB*DD];
__device__ float g_pih[BB*MM];
__device__ float g_proto[MM*NN*DD];
__device__ float g_mixed[NROWS*DD];
__device__ float g_si[NROWS];
__device__ float g_sj[NROWS];
__device__ float g_scores[(size_t)BB*NN*NN];   // 128 MiB (used in 64 MiB halves)
__device__ float g_tv[NROWS*KK];
__device__ int   g_ti[NROWS*KK];
__device__ float g_gnn[NROWS*DD];
__device__ double g_stats[4*DD];

// ---------------- helpers ----------------
__device__ __forceinline__ float nanfix(float x){
  if (isnan(x)) return 0.f;
  if (isinf(x)) return x > 0.f ? 1e4f : -1e4f;
  return x;
}
__device__ __forceinline__ float lrelu(float x){ return x >= 0.f ? x : 0.2f*x; }

__device__ __forceinline__ ull ffma2(ull a, ull b, ull c){
  ull d;
  asm("fma.rn.f32x2 %0, %1, %2, %3;" : "=l"(d) : "l"(a), "l"(b), "l"(c));
  return d;
}
__device__ __forceinline__ ull dup2(float a){
  ull r;
  asm("mov.b64 %0, {%1, %1};" : "=l"(r) : "f"(a));
  return r;
}
__device__ __forceinline__ void unpack2(ull v, float& lo, float& hi){
  asm("mov.b64 {%0, %1}, %2;" : "=f"(lo), "=f"(hi) : "l"(v));
}

// ---------------- K1: cond MLP (h_it, e_it) + x_lin (warp per row) + stats zero ----------------
__global__ void __launch_bounds__(256) k_cond(const float* __restrict__ data,
    const float* __restrict__ Wc, const float* __restrict__ bc,
    const float* __restrict__ Wap, const float* __restrict__ bap,
    const float* __restrict__ Wav, const float* __restrict__ Wg){
  __shared__ float Wap_s[DD*DD];
  __shared__ float Wc_s[FF*DD];
  __shared__ float Wg_s[FF*DD];
  __shared__ float hbuf[8][DD];
  int t = threadIdx.x;
  if (blockIdx.x == 0) g_stats[t] = 0.0;
  for (int e = t; e < DD*DD; e += 256) Wap_s[e] = Wap[e];
  for (int e = t; e < FF*DD; e += 256){ Wc_s[e] = Wc[e]; Wg_s[e] = Wg[e]; }
  __syncthreads();
  int warp = t >> 5, lane = t & 31;
  int row = blockIdx.x*8 + warp;
  const float* dr = data + row*FF;
  float x[FF];
  #pragma unroll
  for (int f = 0; f < FF; f++) x[f] = dr[f];
  int d0 = lane, d1 = lane + 32;
  float h0 = bc[d0], h1 = bc[d1], xl0 = 0.f, xl1 = 0.f;
  #pragma unroll
  for (int f = 0; f < FF; f++){
    h0  = fmaf(x[f], Wc_s[f*DD+d0], h0);
    h1  = fmaf(x[f], Wc_s[f*DD+d1], h1);
    xl0 = fmaf(x[f], Wg_s[f*DD+d0], xl0);
    xl1 = fmaf(x[f], Wg_s[f*DD+d1], xl1);
  }
  g_hit[row*DD+d0] = h0;  g_hit[row*DD+d1] = h1;
  g_xlin[row*DD+d0] = xl0; g_xlin[row*DD+d1] = xl1;
  hbuf[warp][d0] = h0; hbuf[warp][d1] = h1;
  __syncwarp();
  float a0 = bap[d0], a1 = bap[d1];
  #pragma unroll 16
  for (int e = 0; e < DD; e++){
    float he = hbuf[warp][e];
    a0 = fmaf(he, Wap_s[e*DD+d0], a0);
    a1 = fmaf(he, Wap_s[e*DD+d1], a1);
  }
  a0 = lrelu(a0); a1 = lrelu(a1);
  float ts = a0*Wav[d0] + a1*Wav[d1];
  #pragma unroll
  for (int off = 16; off > 0; off >>= 1) ts += __shfl_xor_sync(0xffffffffu, ts, off);
  if (lane == 0) g_eit[row] = nanfix(ts);
}

// ---------------- K2a: per-batch softmax max + denom ----------------
__global__ void __launch_bounds__(256) k_esoft(){
  int b = blockIdx.x, t = threadIdx.x;
  __shared__ float red[256];
  const float* e = g_eit + b*NN;
  float m = fmaxf(e[t], fmaxf(e[t+256], fmaxf(e[t+512], e[t+768])));
  red[t] = m; __syncthreads();
  for (int s = 128; s > 0; s >>= 1){ if (t < s) red[t] = fmaxf(red[t], red[t+s]); __syncthreads(); }
  float mx = red[0];
  __syncthreads();
  float se = expf(e[t]-mx) + expf(e[t+256]-mx) + expf(e[t+512]-mx) + expf(e[t+768]-mx);
  red[t] = se; __syncthreads();
  for (int s = 128; s > 0; s >>= 1){ if (t < s) red[t] += red[t+s]; __syncthreads(); }
  if (t == 0){ g_emax[b] = mx; g_eden[b] = red[0]; }
}

// ---------------- K2b: h_sys partial weighted sums ----------------
__global__ void __launch_bounds__(256) k_hsys(){
  int chunk = blockIdx.x;
  int b = blockIdx.y;
  int t = threadIdx.x;
  int d = t & 63, r4 = t >> 6;
  __shared__ float red[256];
  float mx = g_emax[b];
  int n0 = chunk*64;
  const float* e = g_eit + b*NN + n0;
  const float* h = g_hit + ((size_t)b*NN + n0)*DD;
  float acc = 0.f;
  #pragma unroll 4
  for (int r = r4; r < 64; r += 4)
    acc = fmaf(expf(e[r]-mx), h[r*DD + d], acc);
  red[t] = acc; __syncthreads();
  if (t < 64)
    g_hpart[(chunk*BB + b)*DD + d] = red[d] + red[d+64] + red[d+128] + red[d+192];
}

// ---------------- K2c: finalize h_sys + gumbel top-2 routing ----------------
__global__ void __launch_bounds__(64) k_route(const float* __restrict__ Wr,
    const float* __restrict__ br, const float* __restrict__ gum,
    float* __restrict__ hs_out, float* __restrict__ ps_out){
  int b = blockIdx.x, t = threadIdx.x;
  __shared__ float shs[DD];
  __shared__ float slog[MM];
  float s = 0.f;
  #pragma unroll
  for (int c = 0; c < HCHUNK; c++) s += g_hpart[(c*BB + b)*DD + t];
  float hs = s / g_eden[b];
  shs[t] = hs;
  hs_out[b*DD + t] = hs;
  __syncthreads();
  if (t < MM){
    float lg = br[t] + gum[b*MM + t];
    #pragma unroll 8
    for (int dd2 = 0; dd2 < DD; dd2++) lg = fmaf(shs[dd2], Wr[dd2*MM + t], lg);
    slog[t] = lg;
  }
  __syncthreads();
  if (t == 0){
    float mm = slog[0];
    #pragma unroll
    for (int i = 1; i < MM; i++) mm = fmaxf(mm, slog[i]);
    float p[MM]; float sp = 0.f;
    #pragma unroll
    for (int i = 0; i < MM; i++){ p[i] = expf(slog[i] - mm); sp += p[i]; }
    #pragma unroll
    for (int i = 0; i < MM; i++){ p[i] /= sp; ps_out[b*MM + i] = p[i]; }
    int i1 = 0;
    #pragma unroll
    for (int i = 1; i < MM; i++) if (p[i] > p[i1]) i1 = i;
    int i2 = -1;
    #pragma unroll
    for (int i = 0; i < MM; i++){
      if (i == i1) continue;
      if (i2 < 0 || p[i] > p[i2]) i2 = i;
    }
    float nrm = fmaxf(p[i1] + p[i2], 1e-12f);
    #pragma unroll
    for (int i = 0; i < MM; i++) g_pih[b*MM + i] = 0.f;
    g_pih[b*MM + i1] = p[i1] / nrm;
    g_pih[b*MM + i2] = p[i2] / nrm;
  }
}

// ---------------- K3a: expert prototypes ----------------
__global__ void __launch_bounds__(256) k_proto(const float* __restrict__ ebase,
    const float* __restrict__ lru, const float* __restrict__ lrv){
  int t = threadIdx.x, warp = t >> 5, lane = t & 31;
  int rown = blockIdx.x*8 + warp;
  int m = rown >> 10, n = rown & (NN-1);
  int d0 = lane, d1 = lane + 32;
  float p0 = ebase[n*DD+d0], p1 = ebase[n*DD+d1];
  #pragma unroll
  for (int r = 0; r < RR; r++){
    float u = lru[rown*RR + r];
    p0 = fmaf(u, lrv[(m*RR+r)*DD+d0], p0);
    p1 = fmaf(u, lrv[(m*RR+r)*DD+d1], p1);
  }
  g_proto[rown*DD+d0] = p0;
  g_proto[rown*DD+d1] = p1;
}

// ---------------- K3b: mixed = pi @ proto, + s_i / s_j ----------------
__global__ void __launch_bounds__(256) k_mixed(const float* __restrict__ ai,
    const float* __restrict__ aj, const float* __restrict__ aei,
    const float* __restrict__ aej){
  int t = threadIdx.x, warp = t >> 5, lane = t & 31;
  int row = blockIdx.x*8 + warp;
  int b = row >> 10, n = row & (NN-1);
  int d0 = lane, d1 = lane + 32;
  float pi0 = g_pih[b*MM+0], pi1 = g_pih[b*MM+1];
  float pi2 = g_pih[b*MM+2], pi3 = g_pih[b*MM+3];
  float mx0, mx1;
  {
    const float* p0 = g_proto + (0*NN+n)*DD;
    const float* p1 = g_proto + (1*NN+n)*DD;
    const float* p2 = g_proto + (2*NN+n)*DD;
    const float* p3 = g_proto + (3*NN+n)*DD;
    mx0 = pi0*p0[d0] + pi1*p1[d0] + pi2*p2[d0] + pi3*p3[d0];
    mx1 = pi0*p0[d1] + pi1*p1[d1] + pi2*p2[d1] + pi3*p3[d1];
  }
  mx0 = nanfix(mx0); mx1 = nanfix(mx1);
  g_mixed[row*DD+d0] = mx0;
  g_mixed[row*DD+d1] = mx1;
  float xl0 = g_xlin[row*DD+d0], xl1 = g_xlin[row*DD+d1];
  float r1 = xl0*ai[d0] + mx0*aei[d0] + xl1*ai[d1] + mx1*aei[d1];
  float r2 = xl0*aj[d0] + mx0*aej[d0] + xl1*aj[d1] + mx1*aej[d1];
  #pragma unroll
  for (int off = 16; off > 0; off >>= 1){
    r1 += __shfl_xor_sync(0xffffffffu, r1, off);
    r2 += __shfl_xor_sync(0xffffffffu, r2, off);
  }
  if (lane == 0){ g_si[row] = r1; g_sj[row] = r2; }
}

// ---------------- K4: scores = mixed @ mixed^T (batch chunk), symmetric, f32x2 ----------------
__global__ void __launch_bounds__(256, 2) k_scores(int b0){
  extern __shared__ float smem[];
  float* Ast = smem;               // [64][132]
  float* Bst = smem + 64*132;      // [64][132]
  int b = b0 + blockIdx.z;
  int p = blockIdx.x, ti = 0;
  while (p >= 8 - ti){ p -= 8 - ti; ti++; }
  int tj = ti + p;
  int bi = ti*128, bj = tj*128;
  int t = threadIdx.x;
  const float* A  = g_mixed + ((size_t)b*NN + bi)*DD;
  const float* Bm = g_mixed + ((size_t)b*NN + bj)*DD;
  {
    int i = t >> 1, kh = (t & 1) * 32;
    const float4* a4 = (const float4*)(A  + i*DD + kh);
    const float4* b4 = (const float4*)(Bm + i*DD + kh);
    #pragma unroll
    for (int q = 0; q < 8; q++){
      float4 av = a4[q], bv = b4[q];
      int k = kh + q*4;
      Ast[(k+0)*132 + i] = av.x; Ast[(k+1)*132 + i] = av.y;
      Ast[(k+2)*132 + i] = av.z; Ast[(k+3)*132 + i] = av.w;
      Bst[(k+0)*132 + i] = bv.x; Bst[(k+1)*132 + i] = bv.y;
      Bst[(k+2)*132 + i] = bv.z; Bst[(k+3)*132 + i] = bv.w;
    }
  }
  __syncthreads();
  int tx = t & 15, ty = t >> 4;
  int i0 = ty*8, j0 = tx*8;
  ull acc[8][4];
  #pragma unroll
  for (int ii = 0; ii < 8; ii++)
    #pragma unroll
    for (int jj = 0; jj < 4; jj++) acc[ii][jj] = 0ull;
  #pragma unroll 16
  for (int k = 0; k < 64; k++){
    const float* ar = Ast + k*132 + i0;
    float4 aA = *(const float4*)ar;
    float4 aB = *(const float4*)(ar + 4);
    const ulonglong2* brp = (const ulonglong2*)(Bst + k*132 + j0);
    ulonglong2 b03 = brp[0];
    ulonglong2 b47 = brp[1];
    float av[8] = {aA.x, aA.y, aA.z, aA.w, aB.x, aB.y, aB.z, aB.w};
    #pragma unroll
    for (int ii = 0; ii < 8; ii++){
      ull ad = dup2(av[ii]);
      acc[ii][0] = ffma2(ad, b03.x, acc[ii][0]);
      acc[ii][1] = ffma2(ad, b03.y, acc[ii][1]);
      acc[ii][2] = ffma2(ad, b47.x, acc[ii][2]);
      acc[ii][3] = ffma2(ad, b47.y, acc[ii][3]);
    }
  }
  size_t base = ((size_t)b*NN + bi + i0)*NN + bj + j0;
  #pragma unroll
  for (int ii = 0; ii < 8; ii++){
    ulonglong2* C = (ulonglong2*)(g_scores + base + (size_t)ii*NN);
    C[0] = make_ulonglong2(acc[ii][0], acc[ii][1]);
    C[1] = make_ulonglong2(acc[ii][2], acc[ii][3]);
  }
  if (ti != tj){
    float v[8][8];
    #pragma unroll
    for (int ii = 0; ii < 8; ii++)
      #pragma unroll
      for (int jp = 0; jp < 4; jp++)
        unpack2(acc[ii][jp], v[ii][2*jp], v[ii][2*jp+1]);
    size_t tb = ((size_t)b*NN + bj + j0)*NN + bi + i0;
    #pragma unroll
    for (int jj = 0; jj < 8; jj++){
      float4* C2 = (float4*)(g_scores + tb + (size_t)jj*NN);
      C2[0] = make_float4(v[0][jj], v[1][jj], v[2][jj], v[3][jj]);
      C2[1] = make_float4(v[4][jj], v[5][jj], v[6][jj], v[7][jj]);
    }
  }
}

// ---------------- K5: top-20 per row (warp per row; scores chunk is L2-resident) ----------------
// slot s (0..31) of a lane maps to global j = (s>>2)*128 + lane*4 + (s&3);
// ascending s == ascending j per lane, so tie-breaks match lax.top_k.
__global__ void __launch_bounds__(256) k_topk(int row0){
  int warp = threadIdx.x >> 5, lane = threadIdx.x & 31;
  int row = row0 + blockIdx.x*8 + warp;
  const float4* srow = (const float4*)(g_scores + (size_t)row*NN);
  float v[32];
  #pragma unroll
  for (int c = 0; c < 8; c++){
    float4 q = srow[c*32 + lane];
    v[c*4+0] = q.x; v[c*4+1] = q.y; v[c*4+2] = q.z; v[c*4+3] = q.w;
  }
  float c0v = -CUDART_INF_F, c1v = -CUDART_INF_F, c2v = -CUDART_INF_F;
  int c0s = 0, c1s = 0, c2s = 0;
  #pragma unroll
  for (int s = 0; s < 32; s++){
    float x = v[s];
    if (x > c2v){
      if (x > c1v){
        c2v = c1v; c2s = c1s;
        if (x > c0v){ c1v = c0v; c1s = c0s; c0v = x; c0s = s; }
        else        { c1v = x; c1s = s; }
      } else { c2v = x; c2s = s; }
    }
  }
  unsigned used = 0u;
  int p = 0;
  int cs = c0s;
  float candv = c0v;
  int candg = ((c0s >> 2) << 7) + (lane << 2) + (c0s & 3);
  float* otv = g_tv + row*KK;
  int*   oti = g_ti + row*KK;
  for (int k = 0; k < KK; k++){
    float bv = candv; int bg = candg;
    #pragma unroll
    for (int off = 16; off > 0; off >>= 1){
      float ov = __shfl_xor_sync(0xffffffffu, bv, off);
      int   og = __shfl_xor_sync(0xffffffffu, bg, off);
      if (ov > bv || (ov == bv && og < bg)){ bv = ov; bg = og; }
    }
    if (lane == 0){ otv[k] = bv; oti[k] = bg; }
    if (bg == candg){
      used |= 1u << cs;
      p++;
      if (p == 1){ cs = c1s; candv = c1v; candg = ((c1s>>2)<<7) + (lane<<2) + (c1s&3); }
      else if (p == 2){ cs = c2s; candv = c2v; candg = ((c2s>>2)<<7) + (lane<<2) + (c2s&3); }
      else {
        candv = -CUDART_INF_F; cs = -1;
        #pragma unroll
        for (int s = 0; s < 32; s++){
          if (!((used >> s) & 1u)){
            float x = v[s];
            if (x > candv){ candv = x; cs = s; }
          }
        }
        candg = (cs >= 0) ? (((cs>>2)<<7) + (lane<<2) + (cs&3)) : ((1<<20) + lane);
      }
    }
  }
}

// ---------------- K6: GAT attention + aggregation ----------------
__global__ void __launch_bounds__(256) k_gat(const float* __restrict__ bgnn){
  __shared__ int   sidx[4][KK];
  __shared__ float stv[4][KK];
  __shared__ float sw[4][KK+1];
  int t = threadIdx.x;
  int g = t >> 6, d = t & 63;
  int row = blockIdx.x*4 + g;
  int b = row >> 10, i = row & (NN-1);
  if (d < KK){
    stv[g][d] = g_tv[row*KK + d];
    sidx[g][d] = g_ti[row*KK + d];
  }
  __syncthreads();
  if (d < 32){
    int lane = d;
    float si = g_si[row];
    float a;
    if (lane < KK){
      int j = sidx[g][lane];
      float sj = g_sj[b*NN + j];
      a = (j == i) ? -CUDART_INF_F : lrelu(si + sj);
    } else if (lane == KK){
      a = lrelu(si + g_sj[row]);
    } else a = -CUDART_INF_F;
    float m = a;
    #pragma unroll
    for (int off = 16; off > 0; off >>= 1) m = fmaxf(m, __shfl_xor_sync(0xffffffffu, m, off));
    float e = (lane <= KK) ? expf(a - m) : 0.f;
    float s = e;
    #pragma unroll
    for (int off = 16; off > 0; off >>= 1) s += __shfl_xor_sync(0xffffffffu, s, off);
    float att = e / s;
    float tvv = (lane < KK) ? stv[g][lane] : -CUDART_INF_F;
    float m2 = tvv;
    #pragma unroll
    for (int off = 16; off > 0; off >>= 1) m2 = fmaxf(m2, __shfl_xor_sync(0xffffffffu, m2, off));
    float e2 = (lane < KK) ? expf(tvv - m2) : 0.f;
    float s2 = e2;
    #pragma unroll
    for (int off = 16; off > 0; off >>= 1) s2 += __shfl_xor_sync(0xffffffffu, s2, off);
    if (lane <= KK)
      sw[g][lane] = (lane < KK) ? att * (e2 / s2) : att;
  }
  __syncthreads();
  float acc = sw[g][KK] * g_xlin[row*DD + d];
  #pragma unroll 4
  for (int k = 0; k < KK; k++)
    acc = fmaf(sw[g][k], g_xlin[((size_t)b*NN + sidx[g][k])*DD + d], acc);
  acc += bgnn[d];
  g_gnn[row*DD + d] = acc;
}

// ---------------- K7: BN1 stats ----------------
__global__ void __launch_bounds__(256) k_stats1(){
  __shared__ float ss[256], sq[256];
  int t = threadIdx.x;
  int c = t >> 6, d = t & 63;
  float s = 0.f, q = 0.f;
  int base = blockIdx.x * 256;
  for (int it = 0; it < 64; it++){
    int row = base + it*4 + c;
    float x = g_gnn[row*DD + d];
    s += x;
    q = fmaf(x, x, q);
  }
  ss[t] = s; sq[t] = q;
  __syncthreads();
  if (t < 64){
    double S = (double)ss[t] + ss[t+64] + ss[t+128] + ss[t+192];
    double Q = (double)sq[t] + sq[t+64] + sq[t+128] + sq[t+192];
    atomicAdd(&g_stats[d], S);
    atomicAdd(&g_stats[DD + d], Q);
  }
}

// ---------------- K8: BN2 stats from recomputed y ----------------
__global__ void __launch_bounds__(256) k_bn1mul(const float* __restrict__ g1,
    const float* __restrict__ be1, const float* __restrict__ net){
  __shared__ float ss[256], sq[256];
  int t = threadIdx.x;
  int c = t >> 6, d = t & 63;
  double inv = 1.0 / (double)NROWS;
  double mu = g_stats[d] * inv;
  double var = g_stats[DD + d] * inv - mu*mu;
  float scale = g1[d] * rsqrtf((float)var + BN_EPS);
  float shift = be1[d] - (float)mu * scale;
  float s = 0.f, q = 0.f;
  int base = blockIdx.x * 256;
  for (int it = 0; it < 64; it++){
    int row = base + it*4 + c;
    float x = g_gnn[row*DD + d];
    float gv = fmaxf(fmaf(x, scale, shift), 0.f);
    float y = gv * net[(row & (NN-1))*DD + d];
    s += y;
    q = fmaf(y, y, q);
  }
  ss[t] = s; sq[t] = q;
  __syncthreads();
  if (t < 64){
    double S = (double)ss[t] + ss[t+64] + ss[t+128] + ss[t+192];
    double Q = (double)sq[t] + sq[t+64] + sq[t+128] + sq[t+192];
    atomicAdd(&g_stats[2*DD + d], S);
    atomicAdd(&g_stats[3*DD + d], Q);
  }
}

// ---------------- K9: BN2 + relu + output head ----------------
__global__ void __launch_bounds__(256) k_head(const float* __restrict__ g1,
    const float* __restrict__ be1, const float* __restrict__ net,
    const float* __restrict__ g2, const float* __restrict__ be2,
    const float* __restrict__ Wo, const float* __restrict__ bo,
    float* __restrict__ dout){
  int warp = threadIdx.x >> 5;
  int lane = threadIdx.x & 31;
  int row = blockIdx.x*8 + warp;
  int n = row & (NN-1);
  double inv = 1.0 / (double)NROWS;
  float acc = 0.f;
  #pragma unroll
  for (int h = 0; h < 2; h++){
    int d = lane + h*32;
    double mu1 = g_stats[d] * inv;
    double var1 = g_stats[DD + d] * inv - mu1*mu1;
    float sc1 = g1[d] * rsqrtf((float)var1 + BN_EPS);
    float sh1 = be1[d] - (float)mu1 * sc1;
    double mu2 = g_stats[2*DD + d] * inv;
    double var2 = g_stats[3*DD + d] * inv - mu2*mu2;
    float sc2 = g2[d] * rsqrtf((float)var2 + BN_EPS);
    float sh2 = be2[d] - (float)mu2 * sc2;
    float x = g_gnn[row*DD + d];
    float gv = fmaxf(fmaf(x, sc1, sh1), 0.f);
    float y = gv * net[n*DD + d];
    float r = fmaxf(fmaf(y, sc2, sh2), 0.f);
    acc = fmaf(r, Wo[d], acc);
  }
  #pragma unroll
  for (int off = 16; off > 0; off >>= 1)
    acc += __shfl_down_sync(0xffffffffu, acc, off);
  if (lane == 0) dout[row] = acc + bo[0];
}

// ---------------- launch ----------------
extern "C" void kernel_launch(void* const* d_in, const int* in_sizes, int n_in,
                              void* d_out, int out_size) {
  const float* data   = (const float*)d_in[0];
  const float* gum    = (const float*)d_in[1];
  const float* Wc     = (const float*)d_in[2];
  const float* bc     = (const float*)d_in[3];
  const float* Wap    = (const float*)d_in[4];
  const float* bap    = (const float*)d_in[5];
  const float* Wav    = (const float*)d_in[6];
  const float* Wr     = (const float*)d_in[7];
  const float* br     = (const float*)d_in[8];
  const float* ebase  = (const float*)d_in[9];
  const float* lru    = (const float*)d_in[10];
  const float* lrv    = (const float*)d_in[11];
  const float* Wg     = (const float*)d_in[12];
  const float* ai     = (const float*)d_in[13];
  const float* aj     = (const float*)d_in[14];
  const float* aei    = (const float*)d_in[15];
  const float* aej    = (const float*)d_in[16];
  const float* bgnn   = (const float*)d_in[17];
  const float* g1     = (const float*)d_in[18];
  const float* be1    = (const float*)d_in[19];
  const float* net    = (const float*)d_in[20];
  const float* g2     = (const float*)d_in[21];
  const float* be2    = (const float*)d_in[22];
  const float* Wo     = (const float*)d_in[23];
  const float* bo     = (const float*)d_in[24];

  float* out    = (float*)d_out;              // [B,N]   32768
  float* hs_out = out + NROWS;                // [B,D]   2048
  float* ps_out = hs_out + BB*DD;             // [B,M]   128

  const int SC_SMEM = 2*64*132*4;             // 67584 B
  cudaFuncSetAttribute(k_scores, cudaFuncAttributeMaxDynamicSharedMemorySize, SC_SMEM);

  k_cond<<<NROWS/8, 256>>>(data, Wc, bc, Wap, bap, Wav, Wg);
  k_proto<<<MM*NN/8, 256>>>(ebase, lru, lrv);
  k_esoft<<<BB, 256>>>();
  k_hsys<<<dim3(HCHUNK, BB), 256>>>();
  k_route<<<BB, 64>>>(Wr, br, gum, hs_out, ps_out);
  k_mixed<<<NROWS/8, 256>>>(ai, aj, aei, aej);
  // scores/topk in two 16-batch chunks so each 64 MiB scores slice stays L2-resident
  k_scores<<<dim3(36, 1, HALFB), 256, SC_SMEM>>>(0);
  k_topk<<<HALFB*NN/8, 256>>>(0);
  k_scores<<<dim3(36, 1, HALFB), 256, SC_SMEM>>>(HALFB);
  k_topk<<<HALFB*NN/8, 256>>>(HALFB*NN);
  k_gat<<<NROWS/4, 256>>>(bgnn);
  k_stats1<<<128, 256>>>();
  k_bn1mul<<<128, 256>>>(g1, be1, net);
  k_head<<<NROWS/8, 256>>>(g1, be1, net, g2, be2, Wo, bo, out);
}

// round 13
// speedup vs baseline: 1.5099x; 1.0533x over previous
#include <cuda_runtime.h>
#include <math_constants.h>
#include <math.h>

#define BB 32
#define NN 1024
#define FF 10
#define DD 64
#define MM 4
#define RR 8
#define KK 20
#define NROWS (BB*NN)           // 32768
#define BN_EPS 1e-5f
#define HCHUNK 16

typedef unsigned long long ull;

// ---------------- scratch (device globals; no runtime allocation) ----------------
__device__ float g_hit[NROWS*DD];
__device__ float g_xlin[NROWS*DD];
__device__ float g_eit[NROWS];
__device__ float g_hpart[HCHUNK*BB*DD];
__device__ float g_dpart[HCHUNK*BB];
__device__ float g_pih[BB*MM];
__device__ float g_proto[MM*NN*DD];
__device__ float g_mixed[NROWS*DD];
__device__ float g_si[NROWS];
__device__ float g_sj[NROWS];
__device__ float g_scores[(size_t)BB*NN*NN];   // 128 MiB
__device__ float g_tv[NROWS*KK];
__device__ int   g_ti[NROWS*KK];
__device__ float g_gnn[NROWS*DD];
__device__ double g_stats[4*DD];

// ---------------- helpers ----------------
__device__ __forceinline__ float nanfix(float x){
  if (isnan(x)) return 0.f;
  if (isinf(x)) return x > 0.f ? 1e4f : -1e4f;
  return x;
}
__device__ __forceinline__ float lrelu(float x){ return x >= 0.f ? x : 0.2f*x; }

__device__ __forceinline__ ull ffma2(ull a, ull b, ull c){
  ull d;
  asm("fma.rn.f32x2 %0, %1, %2, %3;" : "=l"(d) : "l"(a), "l"(b), "l"(c));
  return d;
}
__device__ __forceinline__ ull dup2(float a){
  ull r;
  asm("mov.b64 %0, {%1, %1};" : "=l"(r) : "f"(a));
  return r;
}
__device__ __forceinline__ void unpack2(ull v, float& lo, float& hi){
  asm("mov.b64 {%0, %1}, %2;" : "=f"(lo), "=f"(hi) : "l"(v));
}

// ---------------- K1: cond MLP (h_it, e_it) + x_lin + proto fold + stats zero ----------------
__global__ void __launch_bounds__(256) k_cond(const float* __restrict__ data,
    const float* __restrict__ Wc, const float* __restrict__ bc,
    const float* __restrict__ Wap, const float* __restrict__ bap,
    const float* __restrict__ Wav, const float* __restrict__ Wg,
    const float* __restrict__ ebase, const float* __restrict__ lru,
    const float* __restrict__ lrv){
  __shared__ float Wap_s[DD*DD];
  __shared__ float Wc_s[FF*DD];
  __shared__ float Wg_s[FF*DD];
  __shared__ float hbuf[8][DD];
  int t = threadIdx.x;
  if (blockIdx.x == 0) g_stats[t] = 0.0;
  for (int e = t; e < DD*DD; e += 256) Wap_s[e] = Wap[e];
  for (int e = t; e < FF*DD; e += 256){ Wc_s[e] = Wc[e]; Wg_s[e] = Wg[e]; }
  int warp = t >> 5, lane = t & 31;
  int row = blockIdx.x*8 + warp;
  // ---- folded k_proto: blocks 0..511 each handle 8 proto rows ----
  if (blockIdx.x < MM*NN/8){
    int rown = blockIdx.x*8 + warp;        // m*NN + n
    int m = rown >> 10, n = rown & (NN-1);
    int pd0 = lane, pd1 = lane + 32;
    float p0 = ebase[n*DD+pd0], p1 = ebase[n*DD+pd1];
    #pragma unroll
    for (int r = 0; r < RR; r++){
      float u = lru[rown*RR + r];
      p0 = fmaf(u, lrv[(m*RR+r)*DD+pd0], p0);
      p1 = fmaf(u, lrv[(m*RR+r)*DD+pd1], p1);
    }
    g_proto[rown*DD+pd0] = p0;
    g_proto[rown*DD+pd1] = p1;
  }
  __syncthreads();
  const float* dr = data + row*FF;
  float x[FF];
  #pragma unroll
  for (int f = 0; f < FF; f++) x[f] = dr[f];
  int d0 = lane, d1 = lane + 32;
  float h0 = bc[d0], h1 = bc[d1], xl0 = 0.f, xl1 = 0.f;
  #pragma unroll
  for (int f = 0; f < FF; f++){
    h0  = fmaf(x[f], Wc_s[f*DD+d0], h0);
    h1  = fmaf(x[f], Wc_s[f*DD+d1], h1);
    xl0 = fmaf(x[f], Wg_s[f*DD+d0], xl0);
    xl1 = fmaf(x[f], Wg_s[f*DD+d1], xl1);
  }
  g_hit[row*DD+d0] = h0;  g_hit[row*DD+d1] = h1;
  g_xlin[row*DD+d0] = xl0; g_xlin[row*DD+d1] = xl1;
  hbuf[warp][d0] = h0; hbuf[warp][d1] = h1;
  __syncwarp();
  float a0 = bap[d0], a1 = bap[d1];
  #pragma unroll 16
  for (int e = 0; e < DD; e++){
    float he = hbuf[warp][e];
    a0 = fmaf(he, Wap_s[e*DD+d0], a0);
    a1 = fmaf(he, Wap_s[e*DD+d1], a1);
  }
  a0 = lrelu(a0); a1 = lrelu(a1);
  float ts = a0*Wav[d0] + a1*Wav[d1];
  #pragma unroll
  for (int off = 16; off > 0; off >>= 1) ts += __shfl_xor_sync(0xffffffffu, ts, off);
  if (lane == 0) g_eit[row] = nanfix(ts);
}

// ---------------- K2: h_sys partial sums + partial denominators (no-max softmax) ----------------
// e_it is bounded (|e|<~1) by construction, so exp needs no max subtraction.
__global__ void __launch_bounds__(256) k_hsys(){
  int chunk = blockIdx.x;            // 0..15 (64 rows each)
  int b = blockIdx.y;
  int t = threadIdx.x;
  int d = t & 63, r4 = t >> 6;
  __shared__ float we[64];
  __shared__ float red[256];
  int n0 = chunk*64;
  const float* e = g_eit + b*NN + n0;
  if (t < 64) we[t] = expf(e[t]);
  __syncthreads();
  const float* h = g_hit + ((size_t)b*NN + n0)*DD;
  float acc = 0.f;
  #pragma unroll 4
  for (int r = r4; r < 64; r += 4)
    acc = fmaf(we[r], h[r*DD + d], acc);
  red[t] = acc; __syncthreads();
  if (t < 64)
    g_hpart[(chunk*BB + b)*DD + d] = red[d] + red[d+64] + red[d+128] + red[d+192];
  if (t >= 64 && t < 96){
    int lane = t - 64;
    float s = we[lane] + we[lane+32];
    #pragma unroll
    for (int off = 16; off > 0; off >>= 1) s += __shfl_xor_sync(0xffffffffu, s, off);
    if (lane == 0) g_dpart[chunk*BB + b] = s;
  }
}

// ---------------- K3: finalize h_sys + gumbel top-2 routing ----------------
__global__ void __launch_bounds__(64) k_route(const float* __restrict__ Wr,
    const float* __restrict__ br, const float* __restrict__ gum,
    float* __restrict__ hs_out, float* __restrict__ ps_out){
  int b = blockIdx.x, t = threadIdx.x;
  __shared__ float shs[DD];
  __shared__ float slog[MM];
  float s = 0.f;
  #pragma unroll
  for (int c = 0; c < HCHUNK; c++) s += g_hpart[(c*BB + b)*DD + t];
  float den = 0.f;
  #pragma unroll
  for (int c = 0; c < HCHUNK; c++) den += g_dpart[c*BB + b];
  float hs = s / den;
  shs[t] = hs;
  hs_out[b*DD + t] = hs;
  __syncthreads();
  if (t < MM){
    float lg = br[t] + gum[b*MM + t];
    #pragma unroll 8
    for (int dd2 = 0; dd2 < DD; dd2++) lg = fmaf(shs[dd2], Wr[dd2*MM + t], lg);
    slog[t] = lg;
  }
  __syncthreads();
  if (t == 0){
    float mm = slog[0];
    #pragma unroll
    for (int i = 1; i < MM; i++) mm = fmaxf(mm, slog[i]);
    float p[MM]; float sp = 0.f;
    #pragma unroll
    for (int i = 0; i < MM; i++){ p[i] = expf(slog[i] - mm); sp += p[i]; }
    #pragma unroll
    for (int i = 0; i < MM; i++){ p[i] /= sp; ps_out[b*MM + i] = p[i]; }
    int i1 = 0;
    #pragma unroll
    for (int i = 1; i < MM; i++) if (p[i] > p[i1]) i1 = i;
    int i2 = -1;
    #pragma unroll
    for (int i = 0; i < MM; i++){
      if (i == i1) continue;
      if (i2 < 0 || p[i] > p[i2]) i2 = i;
    }
    float nrm = fmaxf(p[i1] + p[i2], 1e-12f);
    #pragma unroll
    for (int i = 0; i < MM; i++) g_pih[b*MM + i] = 0.f;
    g_pih[b*MM + i1] = p[i1] / nrm;
    g_pih[b*MM + i2] = p[i2] / nrm;
  }
}

// ---------------- K4: mixed = pi @ proto, + s_i / s_j ----------------
__global__ void __launch_bounds__(256) k_mixed(const float* __restrict__ ai,
    const float* __restrict__ aj, const float* __restrict__ aei,
    const float* __restrict__ aej){
  int t = threadIdx.x, warp = t >> 5, lane = t & 31;
  int row = blockIdx.x*8 + warp;
  int b = row >> 10, n = row & (NN-1);
  int d0 = lane, d1 = lane + 32;
  float pi0 = g_pih[b*MM+0], pi1 = g_pih[b*MM+1];
  float pi2 = g_pih[b*MM+2], pi3 = g_pih[b*MM+3];
  float mx0, mx1;
  {
    const float* p0 = g_proto + (0*NN+n)*DD;
    const float* p1 = g_proto + (1*NN+n)*DD;
    const float* p2 = g_proto + (2*NN+n)*DD;
    const float* p3 = g_proto + (3*NN+n)*DD;
    mx0 = pi0*p0[d0] + pi1*p1[d0] + pi2*p2[d0] + pi3*p3[d0];
    mx1 = pi0*p0[d1] + pi1*p1[d1] + pi2*p2[d1] + pi3*p3[d1];
  }
  mx0 = nanfix(mx0); mx1 = nanfix(mx1);
  g_mixed[row*DD+d0] = mx0;
  g_mixed[row*DD+d1] = mx1;
  float xl0 = g_xlin[row*DD+d0], xl1 = g_xlin[row*DD+d1];
  float r1 = xl0*ai[d0] + mx0*aei[d0] + xl1*ai[d1] + mx1*aei[d1];
  float r2 = xl0*aj[d0] + mx0*aej[d0] + xl1*aj[d1] + mx1*aej[d1];
  #pragma unroll
  for (int off = 16; off > 0; off >>= 1){
    r1 += __shfl_xor_sync(0xffffffffu, r1, off);
    r2 += __shfl_xor_sync(0xffffffffu, r2, off);
  }
  if (lane == 0){ g_si[row] = r1; g_sj[row] = r2; }
}

// ---------------- K5: scores = mixed @ mixed^T, symmetric, f32x2, 128x128 tiles ----------------
__global__ void __launch_bounds__(256, 2) k_scores(){
  extern __shared__ float smem[];
  float* Ast = smem;               // [64][132]
  float* Bst = smem + 64*132;      // [64][132]
  int b = blockIdx.z;
  int p = blockIdx.x, ti = 0;
  while (p >= 8 - ti){ p -= 8 - ti; ti++; }
  int tj = ti + p;
  int bi = ti*128, bj = tj*128;
  int t = threadIdx.x;
  const float* A  = g_mixed + ((size_t)b*NN + bi)*DD;
  const float* Bm = g_mixed + ((size_t)b*NN + bj)*DD;
  {
    int i = t >> 1, kh = (t & 1) * 32;
    const float4* a4 = (const float4*)(A  + i*DD + kh);
    const float4* b4 = (const float4*)(Bm + i*DD + kh);
    #pragma unroll
    for (int q = 0; q < 8; q++){
      float4 av = a4[q], bv = b4[q];
      int k = kh + q*4;
      Ast[(k+0)*132 + i] = av.x; Ast[(k+1)*132 + i] = av.y;
      Ast[(k+2)*132 + i] = av.z; Ast[(k+3)*132 + i] = av.w;
      Bst[(k+0)*132 + i] = bv.x; Bst[(k+1)*132 + i] = bv.y;
      Bst[(k+2)*132 + i] = bv.z; Bst[(k+3)*132 + i] = bv.w;
    }
  }
  __syncthreads();
  int tx = t & 15, ty = t >> 4;
  int i0 = ty*8, j0 = tx*8;
  ull acc[8][4];
  #pragma unroll
  for (int ii = 0; ii < 8; ii++)
    #pragma unroll
    for (int jj = 0; jj < 4; jj++) acc[ii][jj] = 0ull;
  #pragma unroll 16
  for (int k = 0; k < 64; k++){
    const float* ar = Ast + k*132 + i0;
    float4 aA = *(const float4*)ar;
    float4 aB = *(const float4*)(ar + 4);
    const ulonglong2* brp = (const ulonglong2*)(Bst + k*132 + j0);
    ulonglong2 b03 = brp[0];
    ulonglong2 b47 = brp[1];
    float av[8] = {aA.x, aA.y, aA.z, aA.w, aB.x, aB.y, aB.z, aB.w};
    #pragma unroll
    for (int ii = 0; ii < 8; ii++){
      ull ad = dup2(av[ii]);
      acc[ii][0] = ffma2(ad, b03.x, acc[ii][0]);
      acc[ii][1] = ffma2(ad, b03.y, acc[ii][1]);
      acc[ii][2] = ffma2(ad, b47.x, acc[ii][2]);
      acc[ii][3] = ffma2(ad, b47.y, acc[ii][3]);
    }
  }
  size_t base = ((size_t)b*NN + bi + i0)*NN + bj + j0;
  #pragma unroll
  for (int ii = 0; ii < 8; ii++){
    ulonglong2* C = (ulonglong2*)(g_scores + base + (size_t)ii*NN);
    C[0] = make_ulonglong2(acc[ii][0], acc[ii][1]);
    C[1] = make_ulonglong2(acc[ii][2], acc[ii][3]);
  }
  if (ti != tj){
    float v[8][8];
    #pragma unroll
    for (int ii = 0; ii < 8; ii++)
      #pragma unroll
      for (int jp = 0; jp < 4; jp++)
        unpack2(acc[ii][jp], v[ii][2*jp], v[ii][2*jp+1]);
    size_t tb = ((size_t)b*NN + bj + j0)*NN + bi + i0;
    #pragma unroll
    for (int jj = 0; jj < 8; jj++){
      float4* C2 = (float4*)(g_scores + tb + (size_t)jj*NN);
      C2[0] = make_float4(v[0][jj], v[1][jj], v[2][jj], v[3][jj]);
      C2[1] = make_float4(v[4][jj], v[5][jj], v[6][jj], v[7][jj]);
    }
  }
}

// ---------------- K6: top-20 per row (warp per row, vectorized loads) ----------------
// slot s (0..31) of a lane maps to global j = (s>>2)*128 + lane*4 + (s&3);
// ascending s == ascending j per lane, so tie-breaks match lax.top_k.
__global__ void __launch_bounds__(256) k_topk(){
  int warp = threadIdx.x >> 5, lane = threadIdx.x & 31;
  int row = blockIdx.x*8 + warp;
  const float4* srow = (const float4*)(g_scores + (size_t)row*NN);
  float v[32];
  #pragma unroll
  for (int c = 0; c < 8; c++){
    float4 q = srow[c*32 + lane];
    v[c*4+0] = q.x; v[c*4+1] = q.y; v[c*4+2] = q.z; v[c*4+3] = q.w;
  }
  float c0v = -CUDART_INF_F, c1v = -CUDART_INF_F, c2v = -CUDART_INF_F;
  int c0s = 0, c1s = 0, c2s = 0;
  #pragma unroll
  for (int s = 0; s < 32; s++){
    float x = v[s];
    if (x > c2v){
      if (x > c1v){
        c2v = c1v; c2s = c1s;
        if (x > c0v){ c1v = c0v; c1s = c0s; c0v = x; c0s = s; }
        else        { c1v = x; c1s = s; }
      } else { c2v = x; c2s = s; }
    }
  }
  unsigned used = 0u;
  int p = 0;
  int cs = c0s;
  float candv = c0v;
  int candg = ((c0s >> 2) << 7) + (lane << 2) + (c0s & 3);
  float* otv = g_tv + row*KK;
  int*   oti = g_ti + row*KK;
  for (int k = 0; k < KK; k++){
    float bv = candv; int bg = candg;
    #pragma unroll
    for (int off = 16; off > 0; off >>= 1){
      float ov = __shfl_xor_sync(0xffffffffu, bv, off);
      int   og = __shfl_xor_sync(0xffffffffu, bg, off);
      if (ov > bv || (ov == bv && og < bg)){ bv = ov; bg = og; }
    }
    if (lane == 0){ otv[k] = bv; oti[k] = bg; }
    if (bg == candg){
      used |= 1u << cs;
      p++;
      if (p == 1){ cs = c1s; candv = c1v; candg = ((c1s>>2)<<7) + (lane<<2) + (c1s&3); }
      else if (p == 2){ cs = c2s; candv = c2v; candg = ((c2s>>2)<<7) + (lane<<2) + (c2s&3); }
      else {
        candv = -CUDART_INF_F; cs = -1;
        #pragma unroll
        for (int s = 0; s < 32; s++){
          if (!((used >> s) & 1u)){
            float x = v[s];
            if (x > candv){ candv = x; cs = s; }
          }
        }
        candg = (cs >= 0) ? (((cs>>2)<<7) + (lane<<2) + (cs&3)) : ((1<<20) + lane);
      }
    }
  }
}

// ---------------- K7: GAT attention + aggregation ----------------
__global__ void __launch_bounds__(256) k_gat(const float* __restrict__ bgnn){
  __shared__ int   sidx[4][KK];
  __shared__ float stv[4][KK];
  __shared__ float sw[4][KK+1];
  int t = threadIdx.x;
  int g = t >> 6, d = t & 63;
  int row = blockIdx.x*4 + g;
  int b = row >> 10, i = row & (NN-1);
  if (d < KK){
    stv[g][d] = g_tv[row*KK + d];
    sidx[g][d] = g_ti[row*KK + d];
  }
  __syncthreads();
  if (d < 32){
    int lane = d;
    float si = g_si[row];
    float a;
    if (lane < KK){
      int j = sidx[g][lane];
      float sj = g_sj[b*NN + j];
      a = (j == i) ? -CUDART_INF_F : lrelu(si + sj);
    } else if (lane == KK){
      a = lrelu(si + g_sj[row]);
    } else a = -CUDART_INF_F;
    float m = a;
    #pragma unroll
    for (int off = 16; off > 0; off >>= 1) m = fmaxf(m, __shfl_xor_sync(0xffffffffu, m, off));
    float e = (lane <= KK) ? expf(a - m) : 0.f;
    float s = e;
    #pragma unroll
    for (int off = 16; off > 0; off >>= 1) s += __shfl_xor_sync(0xffffffffu, s, off);
    float att = e / s;
    float tvv = (lane < KK) ? stv[g][lane] : -CUDART_INF_F;
    float m2 = tvv;
    #pragma unroll
    for (int off = 16; off > 0; off >>= 1) m2 = fmaxf(m2, __shfl_xor_sync(0xffffffffu, m2, off));
    float e2 = (lane < KK) ? expf(tvv - m2) : 0.f;
    float s2 = e2;
    #pragma unroll
    for (int off = 16; off > 0; off >>= 1) s2 += __shfl_xor_sync(0xffffffffu, s2, off);
    if (lane <= KK)
      sw[g][lane] = (lane < KK) ? att * (e2 / s2) : att;
  }
  __syncthreads();
  float acc = sw[g][KK] * g_xlin[row*DD + d];
  #pragma unroll 4
  for (int k = 0; k < KK; k++)
    acc = fmaf(sw[g][k], g_xlin[((size_t)b*NN + sidx[g][k])*DD + d], acc);
  acc += bgnn[d];
  g_gnn[row*DD + d] = acc;
}

// ---------------- K8: BN1 stats ----------------
__global__ void __launch_bounds__(256) k_stats1(){
  __shared__ float ss[256], sq[256];
  int t = threadIdx.x;
  int c = t >> 6, d = t & 63;
  float s = 0.f, q = 0.f;
  int base = blockIdx.x * 256;
  for (int it = 0; it < 64; it++){
    int row = base + it*4 + c;
    float x = g_gnn[row*DD + d];
    s += x;
    q = fmaf(x, x, q);
  }
  ss[t] = s; sq[t] = q;
  __syncthreads();
  if (t < 64){
    double S = (double)ss[t] + ss[t+64] + ss[t+128] + ss[t+192];
    double Q = (double)sq[t] + sq[t+64] + sq[t+128] + sq[t+192];
    atomicAdd(&g_stats[d], S);
    atomicAdd(&g_stats[DD + d], Q);
  }
}

// ---------------- K9: BN2 stats from recomputed y ----------------
__global__ void __launch_bounds__(256) k_bn1mul(const float* __restrict__ g1,
    const float* __restrict__ be1, const float* __restrict__ net){
  __shared__ float ss[256], sq[256];
  int t = threadIdx.x;
  int c = t >> 6, d = t & 63;
  double inv = 1.0 / (double)NROWS;
  double mu = g_stats[d] * inv;
  double var = g_stats[DD + d] * inv - mu*mu;
  float scale = g1[d] * rsqrtf((float)var + BN_EPS);
  float shift = be1[d] - (float)mu * scale;
  float s = 0.f, q = 0.f;
  int base = blockIdx.x * 256;
  for (int it = 0; it < 64; it++){
    int row = base + it*4 + c;
    float x = g_gnn[row*DD + d];
    float gv = fmaxf(fmaf(x, scale, shift), 0.f);
    float y = gv * net[(row & (NN-1))*DD + d];
    s += y;
    q = fmaf(y, y, q);
  }
  ss[t] = s; sq[t] = q;
  __syncthreads();
  if (t < 64){
    double S = (double)ss[t] + ss[t+64] + ss[t+128] + ss[t+192];
    double Q = (double)sq[t] + sq[t+64] + sq[t+128] + sq[t+192];
    atomicAdd(&g_stats[2*DD + d], S);
    atomicAdd(&g_stats[3*DD + d], Q);
  }
}

// ---------------- K10: BN2 + relu + output head ----------------
__global__ void __launch_bounds__(256) k_head(const float* __restrict__ g1,
    const float* __restrict__ be1, const float* __restrict__ net,
    const float* __restrict__ g2, const float* __restrict__ be2,
    const float* __restrict__ Wo, const float* __restrict__ bo,
    float* __restrict__ dout){
  int warp = threadIdx.x >> 5;
  int lane = threadIdx.x & 31;
  int row = blockIdx.x*8 + warp;
  int n = row & (NN-1);
  double inv = 1.0 / (double)NROWS;
  float acc = 0.f;
  #pragma unroll
  for (int h = 0; h < 2; h++){
    int d = lane + h*32;
    double mu1 = g_stats[d] * inv;
    double var1 = g_stats[DD + d] * inv - mu1*mu1;
    float sc1 = g1[d] * rsqrtf((float)var1 + BN_EPS);
    float sh1 = be1[d] - (float)mu1 * sc1;
    double mu2 = g_stats[2*DD + d] * inv;
    double var2 = g_stats[3*DD + d] * inv - mu2*mu2;
    float sc2 = g2[d] * rsqrtf((float)var2 + BN_EPS);
    float sh2 = be2[d] - (float)mu2 * sc2;
    float x = g_gnn[row*DD + d];
    float gv = fmaxf(fmaf(x, sc1, sh1), 0.f);
    float y = gv * net[n*DD + d];
    float r = fmaxf(fmaf(y, sc2, sh2), 0.f);
    acc = fmaf(r, Wo[d], acc);
  }
  #pragma unroll
  for (int off = 16; off > 0; off >>= 1)
    acc += __shfl_down_sync(0xffffffffu, acc, off);
  if (lane == 0) dout[row] = acc + bo[0];
}

// ---------------- launch ----------------
extern "C" void kernel_launch(void* const* d_in, const int* in_sizes, int n_in,
                              void* d_out, int out_size) {
  const float* data   = (const float*)d_in[0];
  const float* gum    = (const float*)d_in[1];
  const float* Wc     = (const float*)d_in[2];
  const float* bc     = (const float*)d_in[3];
  const float* Wap    = (const float*)d_in[4];
  const float* bap    = (const float*)d_in[5];
  const float* Wav    = (const float*)d_in[6];
  const float* Wr     = (const float*)d_in[7];
  const float* br     = (const float*)d_in[8];
  const float* ebase  = (const float*)d_in[9];
  const float* lru    = (const float*)d_in[10];
  const float* lrv    = (const float*)d_in[11];
  const float* Wg     = (const float*)d_in[12];
  const float* ai     = (const float*)d_in[13];
  const float* aj     = (const float*)d_in[14];
  const float* aei    = (const float*)d_in[15];
  const float* aej    = (const float*)d_in[16];
  const float* bgnn   = (const float*)d_in[17];
  const float* g1     = (const float*)d_in[18];
  const float* be1    = (const float*)d_in[19];
  const float* net    = (const float*)d_in[20];
  const float* g2     = (const float*)d_in[21];
  const float* be2    = (const float*)d_in[22];
  const float* Wo     = (const float*)d_in[23];
  const float* bo     = (const float*)d_in[24];

  float* out    = (float*)d_out;              // [B,N]   32768
  float* hs_out = out + NROWS;                // [B,D]   2048
  float* ps_out = hs_out + BB*DD;             // [B,M]   128

  const int SC_SMEM = 2*64*132*4;             // 67584 B
  cudaFuncSetAttribute(k_scores, cudaFuncAttributeMaxDynamicSharedMemorySize, SC_SMEM);

  k_cond<<<NROWS/8, 256>>>(data, Wc, bc, Wap, bap, Wav, Wg, ebase, lru, lrv);
  k_hsys<<<dim3(HCHUNK, BB), 256>>>();
  k_route<<<BB, 64>>>(Wr, br, gum, hs_out, ps_out);
  k_mixed<<<NROWS/8, 256>>>(ai, aj, aei, aej);
  k_scores<<<dim3(36, 1, BB), 256, SC_SMEM>>>();
  k_topk<<<NROWS/8, 256>>>();
  k_gat<<<NROWS/4, 256>>>(bgnn);
  k_stats1<<<128, 256>>>();
  k_bn1mul<<<128, 256>>>(g1, be1, net);
  k_head<<<NROWS/8, 256>>>(g1, be1, net, g2, be2, Wo, bo, out);
}